// round 1
// baseline (speedup 1.0000x reference)
#include <cuda_runtime.h>
#include <math.h>

#define NB   4096      // batch
#define LL   128       // leaves
#define EE   128       // embed dim
#define HH   256       // 2*E
#define NOUT 3
#define WPAD 129       // padded row length for transposed W (conflict-free)

// smem: Wt[256][129] + bufA[128][128] + bufB[64][128]
#define SMEM_FLOATS (HH * WPAD + LL * EE + (LL / 2) * EE)
#define SMEM_BYTES  (SMEM_FLOATS * 4)

__device__ int g_tok_is_i32;

// Detect token dtype: if the buffer is int64 (little-endian, tokens < 2^31),
// every odd 32-bit word is zero. If int32, odd words are random tokens in
// [0,100000) — P(2048 consecutive are all zero) ~ 1e-10240. Deterministic.
__global__ void detect_tok_kernel(const unsigned int* __restrict__ w) {
    __shared__ int s;
    if (threadIdx.x == 0) s = 0;
    __syncthreads();
    int any = 0;
    for (int i = threadIdx.x; i < 2048; i += 256)
        any |= (w[2 * i + 1] != 0u);
    if (any) atomicOr(&s, 1);
    __syncthreads();
    if (threadIdx.x == 0) g_tok_is_i32 = s;
}

// One tree level: each thread owns output column e, processes CNT nodes
// starting at nstart. W chunk (16 values) register-cached across nodes;
// node input vectors read as broadcast float4 LDS.
template<int CNT>
__device__ __forceinline__ void level_compute(
    const float* __restrict__ src, float* __restrict__ dst,
    const float* __restrict__ Wt, float bias, int e, int nstart, bool do_store)
{
    float acc[CNT];
#pragma unroll
    for (int i = 0; i < CNT; i++) acc[i] = bias;

#pragma unroll 1
    for (int h0 = 0; h0 < HH; h0 += 16) {
        float w[16];
#pragma unroll
        for (int j = 0; j < 16; j++) w[j] = Wt[(h0 + j) * WPAD + e];
#pragma unroll
        for (int i = 0; i < CNT; i++) {
            const float4* c4 = (const float4*)(src + (nstart + i) * HH + h0);
            float4 a = c4[0], b = c4[1], c = c4[2], d = c4[3];
            float s = acc[i];
            s += w[0]  * a.x; s += w[1]  * a.y; s += w[2]  * a.z; s += w[3]  * a.w;
            s += w[4]  * b.x; s += w[5]  * b.y; s += w[6]  * b.z; s += w[7]  * b.w;
            s += w[8]  * c.x; s += w[9]  * c.y; s += w[10] * c.z; s += w[11] * c.w;
            s += w[12] * d.x; s += w[13] * d.y; s += w[14] * d.z; s += w[15] * d.w;
            acc[i] = s;
        }
    }
    if (do_store) {
#pragma unroll
        for (int i = 0; i < CNT; i++)
            dst[(nstart + i) * EE + e] = tanhf(acc[i]);
    }
}

__global__ __launch_bounds__(256)
void tree_kernel(const void* __restrict__ tokens_raw,
                 const float* __restrict__ emb,
                 const float* __restrict__ W_tree,
                 const float* __restrict__ b_tree,
                 const float* __restrict__ W_cls,
                 const float* __restrict__ b_cls,
                 float* __restrict__ out)
{
    extern __shared__ float smem[];
    float* Wt   = smem;                 // [256][129]
    float* bufA = Wt + HH * WPAD;       // [128][128]
    float* bufB = bufA + LL * EE;       // [64][128]

    const int tid  = threadIdx.x;
    const int b    = blockIdx.x;
    const int e    = tid & 127;
    const int half = tid >> 7;

    // Load W transposed: Wt[h][e] = W_tree[e*256 + h].
    // thread tid = column h; loop k = row e. Global coalesced, smem conflict-free.
#pragma unroll 4
    for (int k = 0; k < EE; k++)
        Wt[tid * WPAD + k] = W_tree[k * HH + tid];

    // Leaf gather: bufA[row][:] = emb[token[row]][:]
    const int is32 = g_tok_is_i32;
    const long long* t64 = (const long long*)tokens_raw;
    const int*       t32 = (const int*)tokens_raw;
    for (int idx = tid; idx < LL * 32; idx += 256) {
        int row = idx >> 5, c4 = idx & 31;
        long long tok = is32 ? (long long)t32[b * LL + row] : t64[b * LL + row];
        ((float4*)bufA)[row * 32 + c4] = ((const float4*)emb)[tok * 32 + c4];
    }

    const float bias = b_tree[e];
    __syncthreads();

    // 7 levels, ping-pong A<->B. concat(left,right) == 256 contiguous floats in src.
    level_compute<32>(bufA, bufB, Wt, bias, e, half * 32, true);  // 128 -> 64
    __syncthreads();
    level_compute<16>(bufB, bufA, Wt, bias, e, half * 16, true);  // 64 -> 32
    __syncthreads();
    level_compute<8>(bufA, bufB, Wt, bias, e, half * 8, true);    // 32 -> 16
    __syncthreads();
    level_compute<4>(bufB, bufA, Wt, bias, e, half * 4, true);    // 16 -> 8
    __syncthreads();
    level_compute<2>(bufA, bufB, Wt, bias, e, half * 2, true);    // 8 -> 4
    __syncthreads();
    level_compute<1>(bufB, bufA, Wt, bias, e, half, true);        // 4 -> 2
    __syncthreads();
    level_compute<1>(bufA, bufB, Wt, bias, e, 0, half == 0);      // 2 -> 1 (root in bufB)
    __syncthreads();

    // Classifier: out[b][o] = b_cls[o] + dot(root, W_cls[o])
    if (tid < 96) {
        int o = tid >> 5, lane = tid & 31;
        float p = 0.f;
#pragma unroll
        for (int k = 0; k < 4; k++) {
            int ee = lane + 32 * k;
            p += bufB[ee] * W_cls[o * EE + ee];
        }
#pragma unroll
        for (int off = 16; off; off >>= 1)
            p += __shfl_down_sync(0xffffffffu, p, off);
        if (lane == 0) out[b * NOUT + o] = p + b_cls[o];
    }
}

extern "C" void kernel_launch(void* const* d_in, const int* in_sizes, int n_in,
                              void* d_out, int out_size)
{
    const void*  tokens = d_in[0];
    const float* emb    = (const float*)d_in[1];
    const float* W_tree = (const float*)d_in[2];
    const float* b_tree = (const float*)d_in[3];
    const float* W_cls  = (const float*)d_in[4];
    const float* b_cls  = (const float*)d_in[5];
    float* out = (float*)d_out;

    cudaFuncSetAttribute(tree_kernel,
                         cudaFuncAttributeMaxDynamicSharedMemorySize, SMEM_BYTES);

    detect_tok_kernel<<<1, 256>>>((const unsigned int*)tokens);
    tree_kernel<<<NB, 256, SMEM_BYTES>>>(tokens, emb, W_tree, b_tree,
                                         W_cls, b_cls, out);
}

// round 2
// speedup vs baseline: 1.0018x; 1.0018x over previous
#include <cuda_runtime.h>
#include <math.h>

#define NB   4096      // batch
#define LL   128       // leaves
#define EE   128       // embed dim
#define HH   256       // 2*E
#define NOUT 3
#define WPAD 129       // padded row length for transposed W (conflict-free)

// smem: Wt[256][129] + bufA[128][128] + bufB[64][128]
#define SMEM_FLOATS (HH * WPAD + LL * EE + (LL / 2) * EE)
#define SMEM_BYTES  (SMEM_FLOATS * 4)

__device__ int g_tok_is_i32;

// Detect token dtype: if the buffer is int64 (little-endian, tokens < 2^31),
// every odd 32-bit word is zero. If int32, odd words are random tokens in
// [0,100000) — P(2048 consecutive are all zero) ~ 1e-10240. Deterministic.
__global__ void detect_tok_kernel(const unsigned int* __restrict__ w) {
    __shared__ int s;
    if (threadIdx.x == 0) s = 0;
    __syncthreads();
    int any = 0;
    for (int i = threadIdx.x; i < 2048; i += 256)
        any |= (w[2 * i + 1] != 0u);
    if (any) atomicOr(&s, 1);
    __syncthreads();
    if (threadIdx.x == 0) g_tok_is_i32 = s;
}

// One tree level: each thread owns output column e, processes CNT nodes
// starting at nstart. W chunk (16 values) register-cached across nodes;
// node input vectors read as broadcast float4 LDS.
template<int CNT>
__device__ __forceinline__ void level_compute(
    const float* __restrict__ src, float* __restrict__ dst,
    const float* __restrict__ Wt, float bias, int e, int nstart, bool do_store)
{
    float acc[CNT];
#pragma unroll
    for (int i = 0; i < CNT; i++) acc[i] = bias;

#pragma unroll 1
    for (int h0 = 0; h0 < HH; h0 += 16) {
        float w[16];
#pragma unroll
        for (int j = 0; j < 16; j++) w[j] = Wt[(h0 + j) * WPAD + e];
#pragma unroll
        for (int i = 0; i < CNT; i++) {
            const float4* c4 = (const float4*)(src + (nstart + i) * HH + h0);
            float4 a = c4[0], b = c4[1], c = c4[2], d = c4[3];
            float s = acc[i];
            s += w[0]  * a.x; s += w[1]  * a.y; s += w[2]  * a.z; s += w[3]  * a.w;
            s += w[4]  * b.x; s += w[5]  * b.y; s += w[6]  * b.z; s += w[7]  * b.w;
            s += w[8]  * c.x; s += w[9]  * c.y; s += w[10] * c.z; s += w[11] * c.w;
            s += w[12] * d.x; s += w[13] * d.y; s += w[14] * d.z; s += w[15] * d.w;
            acc[i] = s;
        }
    }
    if (do_store) {
#pragma unroll
        for (int i = 0; i < CNT; i++)
            dst[(nstart + i) * EE + e] = tanhf(acc[i]);
    }
}

__global__ __launch_bounds__(256)
void tree_kernel(const void* __restrict__ tokens_raw,
                 const float* __restrict__ emb,
                 const float* __restrict__ W_tree,
                 const float* __restrict__ b_tree,
                 const float* __restrict__ W_cls,
                 const float* __restrict__ b_cls,
                 float* __restrict__ out)
{
    extern __shared__ float smem[];
    float* Wt   = smem;                 // [256][129]
    float* bufA = Wt + HH * WPAD;       // [128][128]
    float* bufB = bufA + LL * EE;       // [64][128]

    const int tid  = threadIdx.x;
    const int b    = blockIdx.x;
    const int e    = tid & 127;
    const int half = tid >> 7;

    // Load W transposed: Wt[h][e] = W_tree[e*256 + h].
    // thread tid = column h; loop k = row e. Global coalesced, smem conflict-free.
#pragma unroll 4
    for (int k = 0; k < EE; k++)
        Wt[tid * WPAD + k] = W_tree[k * HH + tid];

    // Leaf gather: bufA[row][:] = emb[token[row]][:]
    const int is32 = g_tok_is_i32;
    const long long* t64 = (const long long*)tokens_raw;
    const int*       t32 = (const int*)tokens_raw;
    for (int idx = tid; idx < LL * 32; idx += 256) {
        int row = idx >> 5, c4 = idx & 31;
        long long tok = is32 ? (long long)t32[b * LL + row] : t64[b * LL + row];
        ((float4*)bufA)[row * 32 + c4] = ((const float4*)emb)[tok * 32 + c4];
    }

    const float bias = b_tree[e];
    __syncthreads();

    // 7 levels, ping-pong A<->B. concat(left,right) == 256 contiguous floats in src.
    level_compute<32>(bufA, bufB, Wt, bias, e, half * 32, true);  // 128 -> 64
    __syncthreads();
    level_compute<16>(bufB, bufA, Wt, bias, e, half * 16, true);  // 64 -> 32
    __syncthreads();
    level_compute<8>(bufA, bufB, Wt, bias, e, half * 8, true);    // 32 -> 16
    __syncthreads();
    level_compute<4>(bufB, bufA, Wt, bias, e, half * 4, true);    // 16 -> 8
    __syncthreads();
    level_compute<2>(bufA, bufB, Wt, bias, e, half * 2, true);    // 8 -> 4
    __syncthreads();
    level_compute<1>(bufB, bufA, Wt, bias, e, half, true);        // 4 -> 2
    __syncthreads();
    level_compute<1>(bufA, bufB, Wt, bias, e, 0, half == 0);      // 2 -> 1 (root in bufB)
    __syncthreads();

    // Classifier: out[b][o] = b_cls[o] + dot(root, W_cls[o])
    if (tid < 96) {
        int o = tid >> 5, lane = tid & 31;
        float p = 0.f;
#pragma unroll
        for (int k = 0; k < 4; k++) {
            int ee = lane + 32 * k;
            p += bufB[ee] * W_cls[o * EE + ee];
        }
#pragma unroll
        for (int off = 16; off; off >>= 1)
            p += __shfl_down_sync(0xffffffffu, p, off);
        if (lane == 0) out[b * NOUT + o] = p + b_cls[o];
    }
}

extern "C" void kernel_launch(void* const* d_in, const int* in_sizes, int n_in,
                              void* d_out, int out_size)
{
    const void*  tokens = d_in[0];
    const float* emb    = (const float*)d_in[1];
    const float* W_tree = (const float*)d_in[2];
    const float* b_tree = (const float*)d_in[3];
    const float* W_cls  = (const float*)d_in[4];
    const float* b_cls  = (const float*)d_in[5];
    float* out = (float*)d_out;

    cudaFuncSetAttribute(tree_kernel,
                         cudaFuncAttributeMaxDynamicSharedMemorySize, SMEM_BYTES);

    detect_tok_kernel<<<1, 256>>>((const unsigned int*)tokens);
    tree_kernel<<<NB, 256, SMEM_BYTES>>>(tokens, emb, W_tree, b_tree,
                                         W_cls, b_cls, out);
}

// round 4
// speedup vs baseline: 2.3931x; 2.3889x over previous
#include <cuda_runtime.h>
#include <cuda_bf16.h>
#include <stdint.h>

#define NB   4096
#define LL   128
#define EE   128
#define NOUTC 3

// ---- shared memory layout (bytes) ----
// ROOT: 128 f32
// W:    hi 4 chunks x [128 rows x 128B] + lo 4 chunks   (131072)
// B0:   hi 4 chunks x [64 x 128B] + lo                  (65536)
// B1:   hi 4 chunks x [32 x 128B] + lo                  (32768)
#define OFF_ROOT 0
#define OFF_W    1024
#define W_CS     16384
#define OFF_B0   (OFF_W + 8 * W_CS)        // 132096
#define B0_CS    8192
#define OFF_B1   (OFF_B0 + 8 * B0_CS)      // 197632
#define B1_CS    4096
#define SMEM_BYTES (OFF_B1 + 8 * B1_CS)    // 230400

__device__ int g_tok_is_i32;

__global__ void detect_tok_kernel(const unsigned int* __restrict__ w) {
    __shared__ int s;
    if (threadIdx.x == 0) s = 0;
    __syncthreads();
    int any = 0;
    for (int i = threadIdx.x; i < 2048; i += 256)
        any |= (w[2 * i + 1] != 0u);
    if (any) atomicOr(&s, 1);
    __syncthreads();
    if (threadIdx.x == 0) g_tok_is_i32 = s;
}

static __device__ __forceinline__ uint32_t sw128(uint32_t b) {
    return b ^ ((b >> 3) & 0x70);
}
static __device__ __forceinline__ uint32_t smem_u32(const void* p) {
    uint32_t a;
    asm("{ .reg .u64 t; cvta.to.shared.u64 t, %1; cvt.u32.u64 %0, t; }" : "=r"(a) : "l"(p));
    return a;
}
static __device__ __forceinline__ void ldsm4(uint32_t addr, uint32_t& r0, uint32_t& r1,
                                             uint32_t& r2, uint32_t& r3) {
    asm volatile("ldmatrix.sync.aligned.m8n8.x4.shared.b16 {%0,%1,%2,%3}, [%4];"
                 : "=r"(r0), "=r"(r1), "=r"(r2), "=r"(r3) : "r"(addr));
}
static __device__ __forceinline__ void mma_bf16(float& d0, float& d1, float& d2, float& d3,
                                                const uint32_t a[4], uint32_t b0, uint32_t b1) {
    asm volatile("mma.sync.aligned.m16n8k16.row.col.f32.bf16.bf16.f32 "
                 "{%0,%1,%2,%3}, {%4,%5,%6,%7}, {%8,%9}, {%0,%1,%2,%3};"
                 : "+f"(d0), "+f"(d1), "+f"(d2), "+f"(d3)
                 : "r"(a[0]), "r"(a[1]), "r"(a[2]), "r"(a[3]), "r"(b0), "r"(b1));
}
static __device__ __forceinline__ float tanh_fast(float x) {
    float t = __expf(2.0f * x);
    return 1.0f - __fdividef(2.0f, t + 1.0f);
}
// split fp32 -> bf16 hi/lo, store at concat position k for next-level row r
static __device__ __forceinline__ void store_out(char* sm, uint32_t dstHi, uint32_t dcs,
                                                 int r, int k, float x) {
    __nv_bfloat16 h = __float2bfloat16(x);
    __nv_bfloat16 l = __float2bfloat16(x - __bfloat162float(h));
    int chunk = k >> 6;
    uint32_t off = sw128((uint32_t)(r * 128 + (k & 63) * 2));
    *(__nv_bfloat16*)(sm + dstHi + (uint32_t)chunk * dcs + off) = h;
    *(__nv_bfloat16*)(sm + dstHi + 4u * dcs + (uint32_t)chunk * dcs + off) = l;
}

// One level: D[e][n] = sum_k W[e][k]*src[n][k]; out = tanh(D+b).
// 8 warps: warp wq owns e rows [16wq,16wq+16), all n tiles.
template<int NTILES, int NOUTV, bool LAST>
static __device__ __forceinline__ void run_level(
    char* sm, uint32_t sb, uint32_t srcHi, uint32_t scs, uint32_t dstHi, uint32_t dcs,
    const uint32_t Ah[16][4], const uint32_t Al[16][4],
    float bias0, float bias1, int wq, int lane, float* rootp)
{
    const int g = lane >> 3, lr = lane & 7;
#pragma unroll 1
    for (int nb = 0; nb < NTILES; nb++) {
        float d0 = bias0, d1 = bias0, d2 = bias1, d3 = bias1;
        uint32_t Bh[16][2];
        const int row = nb * 8 + lr;
#pragma unroll
        for (int j = 0; j < 8; j++) {              // B hi: 2 k-tiles per x4
            int kb = j * 64 + g * 16;
            uint32_t addr = sb + srcHi + (uint32_t)((kb >> 7) * scs)
                          + sw128((uint32_t)(row * 128 + (kb & 127)));
            ldsm4(addr, Bh[2 * j][0], Bh[2 * j][1], Bh[2 * j + 1][0], Bh[2 * j + 1][1]);
        }
#pragma unroll
        for (int kt = 0; kt < 16; kt++)            // Ah * Bh
            mma_bf16(d0, d1, d2, d3, Ah[kt], Bh[kt][0], Bh[kt][1]);
#pragma unroll
        for (int kt = 0; kt < 16; kt++)            // Al * Bh
            mma_bf16(d0, d1, d2, d3, Al[kt], Bh[kt][0], Bh[kt][1]);
#pragma unroll
        for (int j = 0; j < 8; j++) {              // Ah * Bl (streamed)
            int kb = j * 64 + g * 16;
            uint32_t addr = sb + srcHi + 4u * scs + (uint32_t)((kb >> 7) * scs)
                          + sw128((uint32_t)(row * 128 + (kb & 127)));
            uint32_t b0, b1, b2, b3;
            ldsm4(addr, b0, b1, b2, b3);
            mma_bf16(d0, d1, d2, d3, Ah[2 * j], b0, b1);
            mma_bf16(d0, d1, d2, d3, Ah[2 * j + 1], b2, b3);
        }
        // epilogue: lane holds (e0, n), (e0, n+1), (e0+8, n), (e0+8, n+1)
        const int e0 = wq * 16 + (lane >> 2);
        const int nL = nb * 8 + 2 * (lane & 3);
        if constexpr (!LAST) {
            if (nL + 1 < NOUTV || NTILES * 8 == NOUTV) {
                int r = nL >> 1;
                store_out(sm, dstHi, dcs, r, e0,        tanh_fast(d0));
                store_out(sm, dstHi, dcs, r, 128 + e0,  tanh_fast(d1));
                store_out(sm, dstHi, dcs, r, e0 + 8,    tanh_fast(d2));
                store_out(sm, dstHi, dcs, r, 136 + e0,  tanh_fast(d3));
            }
        } else {
            if ((lane & 3) == 0) {
                rootp[e0]     = tanh_fast(d0);
                rootp[e0 + 8] = tanh_fast(d2);
            }
        }
    }
}

__global__ __launch_bounds__(256, 1)
void tree_kernel(const void* __restrict__ tokens_raw,
                 const float* __restrict__ emb,
                 const float* __restrict__ W_tree,
                 const float* __restrict__ b_tree,
                 const float* __restrict__ W_cls,
                 const float* __restrict__ b_cls,
                 float* __restrict__ out)
{
    extern __shared__ char sm[];
    const uint32_t sb = smem_u32(sm);
    const int tid = threadIdx.x, wq = tid >> 5, lane = tid & 31;
    const int b = blockIdx.x;

    // ---- stage W as bf16 hi/lo, sw128 chunked [e][k] ----
    for (int idx = tid; idx < 128 * 64; idx += 256) {
        int e = idx >> 6, q = idx & 63, h = q * 4;
        float4 w = ((const float4*)W_tree)[idx];
        int chunk = h >> 6, inner = h & 63;
        uint32_t off = sw128((uint32_t)(e * 128 + inner * 2));
        char* hiT = sm + OFF_W + chunk * W_CS;
        char* loT = hiT + 4 * W_CS;
        __nv_bfloat16 h0 = __float2bfloat16(w.x), h1 = __float2bfloat16(w.y);
        __nv_bfloat16 h2 = __float2bfloat16(w.z), h3 = __float2bfloat16(w.w);
        __nv_bfloat16 l0 = __float2bfloat16(w.x - __bfloat162float(h0));
        __nv_bfloat16 l1 = __float2bfloat16(w.y - __bfloat162float(h1));
        __nv_bfloat16 l2 = __float2bfloat16(w.z - __bfloat162float(h2));
        __nv_bfloat16 l3 = __float2bfloat16(w.w - __bfloat162float(h3));
        *(uint32_t*)(hiT + off)     = ((uint32_t)*(uint16_t*)&h1 << 16) | *(uint16_t*)&h0;
        *(uint32_t*)(hiT + off + 4) = ((uint32_t)*(uint16_t*)&h3 << 16) | *(uint16_t*)&h2;
        *(uint32_t*)(loT + off)     = ((uint32_t)*(uint16_t*)&l1 << 16) | *(uint16_t*)&l0;
        *(uint32_t*)(loT + off + 4) = ((uint32_t)*(uint16_t*)&l3 << 16) | *(uint16_t*)&l2;
    }

    // ---- leaf gather -> B0: row = pair, k = (leaf&1)*128 + e ----
    const int is32 = g_tok_is_i32;
    const long long* t64 = (const long long*)tokens_raw;
    const int*       t32 = (const int*)tokens_raw;
    for (int idx = tid; idx < 128 * 32; idx += 256) {
        int l = idx >> 5, q = idx & 31;
        long long tok = is32 ? (long long)t32[b * LL + l] : t64[b * LL + l];
        float4 v = ((const float4*)emb)[tok * 32 + q];
        int row = l >> 1, kb16 = ((l & 1) << 7) + q * 4;
        int chunk = kb16 >> 6, inner = kb16 & 63;
        uint32_t off = sw128((uint32_t)(row * 128 + inner * 2));
        char* hiT = sm + OFF_B0 + chunk * B0_CS;
        char* loT = hiT + 4 * B0_CS;
        __nv_bfloat16 h0 = __float2bfloat16(v.x), h1 = __float2bfloat16(v.y);
        __nv_bfloat16 h2 = __float2bfloat16(v.z), h3 = __float2bfloat16(v.w);
        __nv_bfloat16 l0 = __float2bfloat16(v.x - __bfloat162float(h0));
        __nv_bfloat16 l1 = __float2bfloat16(v.y - __bfloat162float(h1));
        __nv_bfloat16 l2 = __float2bfloat16(v.z - __bfloat162float(h2));
        __nv_bfloat16 l3 = __float2bfloat16(v.w - __bfloat162float(h3));
        *(uint32_t*)(hiT + off)     = ((uint32_t)*(uint16_t*)&h1 << 16) | *(uint16_t*)&h0;
        *(uint32_t*)(hiT + off + 4) = ((uint32_t)*(uint16_t*)&h3 << 16) | *(uint16_t*)&h2;
        *(uint32_t*)(loT + off)     = ((uint32_t)*(uint16_t*)&l1 << 16) | *(uint16_t*)&l0;
        *(uint32_t*)(loT + off + 4) = ((uint32_t)*(uint16_t*)&l3 << 16) | *(uint16_t*)&l2;
    }
    __syncthreads();

    // ---- load this warp's W fragments into registers (persist all levels) ----
    uint32_t Ah[16][4], Al[16][4];
    {
        const int g = lane >> 3, lr = lane & 7;
        const int row = wq * 16 + lr + (g & 1) * 8;
#pragma unroll
        for (int kt = 0; kt < 16; kt++) {
            int kb = kt * 32 + (g >> 1) * 16;
            uint32_t off = (uint32_t)((kb >> 7) * W_CS)
                         + sw128((uint32_t)(row * 128 + (kb & 127)));
            ldsm4(sb + OFF_W + off, Ah[kt][0], Ah[kt][1], Ah[kt][2], Ah[kt][3]);
            ldsm4(sb + OFF_W + 4 * W_CS + off, Al[kt][0], Al[kt][1], Al[kt][2], Al[kt][3]);
        }
    }
    const float bias0 = b_tree[wq * 16 + (lane >> 2)];
    const float bias1 = b_tree[wq * 16 + (lane >> 2) + 8];
    float* rootp = (float*)(sm + OFF_ROOT);

    run_level<8, 64, false>(sm, sb, OFF_B0, B0_CS, OFF_B1, B1_CS, Ah, Al, bias0, bias1, wq, lane, rootp);
    __syncthreads();
    run_level<4, 32, false>(sm, sb, OFF_B1, B1_CS, OFF_B0, B0_CS, Ah, Al, bias0, bias1, wq, lane, rootp);
    __syncthreads();
    run_level<2, 16, false>(sm, sb, OFF_B0, B0_CS, OFF_B1, B1_CS, Ah, Al, bias0, bias1, wq, lane, rootp);
    __syncthreads();
    run_level<1, 8, false>(sm, sb, OFF_B1, B1_CS, OFF_B0, B0_CS, Ah, Al, bias0, bias1, wq, lane, rootp);
    __syncthreads();
    run_level<1, 4, false>(sm, sb, OFF_B0, B0_CS, OFF_B1, B1_CS, Ah, Al, bias0, bias1, wq, lane, rootp);
    __syncthreads();
    run_level<1, 2, false>(sm, sb, OFF_B1, B1_CS, OFF_B0, B0_CS, Ah, Al, bias0, bias1, wq, lane, rootp);
    __syncthreads();
    run_level<1, 1, true >(sm, sb, OFF_B0, B0_CS, OFF_B1, B1_CS, Ah, Al, bias0, bias1, wq, lane, rootp);
    __syncthreads();

    // ---- classifier on fp32 root ----
    if (tid < 96) {
        int o = tid >> 5, l2 = tid & 31;
        float p = 0.f;
#pragma unroll
        for (int k = 0; k < 4; k++) {
            int ee = l2 + 32 * k;
            p += rootp[ee] * W_cls[o * EE + ee];
        }
#pragma unroll
        for (int off = 16; off; off >>= 1)
            p += __shfl_down_sync(0xffffffffu, p, off);
        if (l2 == 0) out[b * NOUTC + o] = p + b_cls[o];
    }
}

extern "C" void kernel_launch(void* const* d_in, const int* in_sizes, int n_in,
                              void* d_out, int out_size)
{
    const void*  tokens = d_in[0];
    const float* emb    = (const float*)d_in[1];
    const float* W_tree = (const float*)d_in[2];
    const float* b_tree = (const float*)d_in[3];
    const float* W_cls  = (const float*)d_in[4];
    const float* b_cls  = (const float*)d_in[5];
    float* out = (float*)d_out;

    cudaFuncSetAttribute(tree_kernel,
                         cudaFuncAttributeMaxDynamicSharedMemorySize, SMEM_BYTES);

    detect_tok_kernel<<<1, 256>>>((const unsigned int*)tokens);
    tree_kernel<<<NB, 256, SMEM_BYTES>>>(tokens, emb, W_tree, b_tree,
                                         W_cls, b_cls, out);
}

// round 7
// speedup vs baseline: 2.6404x; 1.1033x over previous
#include <cuda_runtime.h>
#include <cuda_bf16.h>
#include <stdint.h>

#define NB   4096
#define LL   128
#define EE   128
#define NOUTC 3

// ---- shared memory layout (bytes) ----
#define OFF_ROOT 0
#define OFF_W    1024
#define W_CS     16384
#define OFF_B0   (OFF_W + 8 * W_CS)        // 132096
#define B0_CS    8192
#define OFF_B1   (OFF_B0 + 8 * B0_CS)      // 197632
#define B1_CS    4096
#define SMEM_BYTES (OFF_B1 + 8 * B1_CS)    // 230400

__device__ int g_tok_is_i32;

__global__ void detect_tok_kernel(const unsigned int* __restrict__ w) {
    __shared__ int s;
    if (threadIdx.x == 0) s = 0;
    __syncthreads();
    int any = 0;
    for (int i = threadIdx.x; i < 2048; i += 256)
        any |= (w[2 * i + 1] != 0u);
    if (any) atomicOr(&s, 1);
    __syncthreads();
    if (threadIdx.x == 0) g_tok_is_i32 = s;
}

static __device__ __forceinline__ uint32_t sw128(uint32_t b) {
    return b ^ ((b >> 3) & 0x70);
}
static __device__ __forceinline__ uint32_t smem_u32(const void* p) {
    uint32_t a;
    asm("{ .reg .u64 t; cvta.to.shared.u64 t, %1; cvt.u32.u64 %0, t; }" : "=r"(a) : "l"(p));
    return a;
}
static __device__ __forceinline__ void ldsm4(uint32_t addr, uint32_t& r0, uint32_t& r1,
                                             uint32_t& r2, uint32_t& r3) {
    asm volatile("ldmatrix.sync.aligned.m8n8.x4.shared.b16 {%0,%1,%2,%3}, [%4];"
                 : "=r"(r0), "=r"(r1), "=r"(r2), "=r"(r3) : "r"(addr));
}
static __device__ __forceinline__ void mma_bf16(float& d0, float& d1, float& d2, float& d3,
                                                const uint32_t a[4], uint32_t b0, uint32_t b1) {
    asm volatile("mma.sync.aligned.m16n8k16.row.col.f32.bf16.bf16.f32 "
                 "{%0,%1,%2,%3}, {%4,%5,%6,%7}, {%8,%9}, {%0,%1,%2,%3};"
                 : "+f"(d0), "+f"(d1), "+f"(d2), "+f"(d3)
                 : "r"(a[0]), "r"(a[1]), "r"(a[2]), "r"(a[3]), "r"(b0), "r"(b1));
}
static __device__ __forceinline__ float tanh_fast(float x) {
    float t = __expf(2.0f * x);
    return 1.0f - __fdividef(2.0f, t + 1.0f);
}
static __device__ __forceinline__ void store_out(char* sm, uint32_t dstHi, uint32_t dcs,
                                                 int r, int k, float x) {
    __nv_bfloat16 h = __float2bfloat16(x);
    __nv_bfloat16 l = __float2bfloat16(x - __bfloat162float(h));
    int chunk = k >> 6;
    uint32_t off = sw128((uint32_t)(r * 128 + (k & 63) * 2));
    *(__nv_bfloat16*)(sm + dstHi + (uint32_t)chunk * dcs + off) = h;
    *(__nv_bfloat16*)(sm + dstHi + 4u * dcs + (uint32_t)chunk * dcs + off) = l;
}

// One level: D[e][n] = sum_k W[e][k]*src[n][k]; out = tanh(D+b).
// Three independent MMA accumulation chains (Ah*Bh, Al*Bh, Ah*Bl) to hide
// HMMA latency; all B fragments (hi+lo) preloaded before the MMA loop.
template<int NTILES, int NOUTV, bool LAST>
static __device__ __forceinline__ void run_level(
    char* sm, uint32_t sb, uint32_t srcHi, uint32_t scs, uint32_t dstHi, uint32_t dcs,
    const uint32_t Ah[16][4], const uint32_t Al[16][4],
    float bias0, float bias1, int wq, int lane, float* rootp)
{
    const int g = lane >> 3, lr = lane & 7;
#pragma unroll 1
    for (int nb = 0; nb < NTILES; nb++) {
        uint32_t Bh[16][2], Bl[16][2];
        const int row = nb * 8 + lr;
#pragma unroll
        for (int j = 0; j < 8; j++) {              // B hi: 2 k-tiles per x4
            int kb = j * 64 + g * 16;
            uint32_t off = (uint32_t)((kb >> 7) * scs)
                         + sw128((uint32_t)(row * 128 + (kb & 127)));
            ldsm4(sb + srcHi + off,
                  Bh[2 * j][0], Bh[2 * j][1], Bh[2 * j + 1][0], Bh[2 * j + 1][1]);
        }
#pragma unroll
        for (int j = 0; j < 8; j++) {              // B lo
            int kb = j * 64 + g * 16;
            uint32_t off = (uint32_t)((kb >> 7) * scs)
                         + sw128((uint32_t)(row * 128 + (kb & 127)));
            ldsm4(sb + srcHi + 4u * scs + off,
                  Bl[2 * j][0], Bl[2 * j][1], Bl[2 * j + 1][0], Bl[2 * j + 1][1]);
        }

        float c10 = 0.f, c11 = 0.f, c12 = 0.f, c13 = 0.f;   // Ah*Bh
        float c20 = 0.f, c21 = 0.f, c22 = 0.f, c23 = 0.f;   // Al*Bh
        float c30 = 0.f, c31 = 0.f, c32 = 0.f, c33 = 0.f;   // Ah*Bl
#pragma unroll
        for (int kt = 0; kt < 16; kt++) {
            mma_bf16(c10, c11, c12, c13, Ah[kt], Bh[kt][0], Bh[kt][1]);
            mma_bf16(c20, c21, c22, c23, Al[kt], Bh[kt][0], Bh[kt][1]);
            mma_bf16(c30, c31, c32, c33, Ah[kt], Bl[kt][0], Bl[kt][1]);
        }
        float d0 = (bias0 + c10) + (c20 + c30);
        float d1 = (bias0 + c11) + (c21 + c31);
        float d2 = (bias1 + c12) + (c22 + c32);
        float d3 = (bias1 + c13) + (c23 + c33);

        const int e0 = wq * 16 + (lane >> 2);
        const int nL = nb * 8 + 2 * (lane & 3);
        if constexpr (!LAST) {
            if (nL + 1 < NOUTV || NTILES * 8 == NOUTV) {
                int r = nL >> 1;
                store_out(sm, dstHi, dcs, r, e0,        tanh_fast(d0));
                store_out(sm, dstHi, dcs, r, 128 + e0,  tanh_fast(d1));
                store_out(sm, dstHi, dcs, r, e0 + 8,    tanh_fast(d2));
                store_out(sm, dstHi, dcs, r, 136 + e0,  tanh_fast(d3));
            }
        } else {
            if ((lane & 3) == 0) {
                rootp[e0]     = tanh_fast(d0);
                rootp[e0 + 8] = tanh_fast(d2);
            }
        }
    }
}

__global__ __launch_bounds__(256, 1)
void tree_kernel(const void* __restrict__ tokens_raw,
                 const float* __restrict__ emb,
                 const float* __restrict__ W_tree,
                 const float* __restrict__ b_tree,
                 const float* __restrict__ W_cls,
                 const float* __restrict__ b_cls,
                 float* __restrict__ out)
{
    extern __shared__ char sm[];
    const uint32_t sb = smem_u32(sm);
    const int tid = threadIdx.x, wq = tid >> 5, lane = tid & 31;
    const int b = blockIdx.x;

    // ---- stage W as bf16 hi/lo, sw128 chunked [e][k] ----
    for (int idx = tid; idx < 128 * 64; idx += 256) {
        int e = idx >> 6, q = idx & 63, h = q * 4;
        float4 w = ((const float4*)W_tree)[idx];
        int chunk = h >> 6, inner = h & 63;
        uint32_t off = sw128((uint32_t)(e * 128 + inner * 2));
        char* hiT = sm + OFF_W + chunk * W_CS;
        char* loT = hiT + 4 * W_CS;
        __nv_bfloat16 h0 = __float2bfloat16(w.x), h1 = __float2bfloat16(w.y);
        __nv_bfloat16 h2 = __float2bfloat16(w.z), h3 = __float2bfloat16(w.w);
        __nv_bfloat16 l0 = __float2bfloat16(w.x - __bfloat162float(h0));
        __nv_bfloat16 l1 = __float2bfloat16(w.y - __bfloat162float(h1));
        __nv_bfloat16 l2 = __float2bfloat16(w.z - __bfloat162float(h2));
        __nv_bfloat16 l3 = __float2bfloat16(w.w - __bfloat162float(h3));
        *(uint32_t*)(hiT + off)     = ((uint32_t)*(uint16_t*)&h1 << 16) | *(uint16_t*)&h0;
        *(uint32_t*)(hiT + off + 4) = ((uint32_t)*(uint16_t*)&h3 << 16) | *(uint16_t*)&h2;
        *(uint32_t*)(loT + off)     = ((uint32_t)*(uint16_t*)&l1 << 16) | *(uint16_t*)&l0;
        *(uint32_t*)(loT + off + 4) = ((uint32_t)*(uint16_t*)&l3 << 16) | *(uint16_t*)&l2;
    }

    // ---- leaf gather -> B0: row = pair, k = (leaf&1)*128 + e ----
    const int is32 = g_tok_is_i32;
    const long long* t64 = (const long long*)tokens_raw;
    const int*       t32 = (const int*)tokens_raw;
    for (int idx = tid; idx < 128 * 32; idx += 256) {
        int l = idx >> 5, q = idx & 31;
        long long tok = is32 ? (long long)t32[b * LL + l] : t64[b * LL + l];
        float4 v = ((const float4*)emb)[tok * 32 + q];
        int row = l >> 1, kb16 = ((l & 1) << 7) + q * 4;
        int chunk = kb16 >> 6, inner = kb16 & 63;
        uint32_t off = sw128((uint32_t)(row * 128 + inner * 2));
        char* hiT = sm + OFF_B0 + chunk * B0_CS;
        char* loT = hiT + 4 * B0_CS;
        __nv_bfloat16 h0 = __float2bfloat16(v.x), h1 = __float2bfloat16(v.y);
        __nv_bfloat16 h2 = __float2bfloat16(v.z), h3 = __float2bfloat16(v.w);
        __nv_bfloat16 l0 = __float2bfloat16(v.x - __bfloat162float(h0));
        __nv_bfloat16 l1 = __float2bfloat16(v.y - __bfloat162float(h1));
        __nv_bfloat16 l2 = __float2bfloat16(v.z - __bfloat162float(h2));
        __nv_bfloat16 l3 = __float2bfloat16(v.w - __bfloat162float(h3));
        *(uint32_t*)(hiT + off)     = ((uint32_t)*(uint16_t*)&h1 << 16) | *(uint16_t*)&h0;
        *(uint32_t*)(hiT + off + 4) = ((uint32_t)*(uint16_t*)&h3 << 16) | *(uint16_t*)&h2;
        *(uint32_t*)(loT + off)     = ((uint32_t)*(uint16_t*)&l1 << 16) | *(uint16_t*)&l0;
        *(uint32_t*)(loT + off + 4) = ((uint32_t)*(uint16_t*)&l3 << 16) | *(uint16_t*)&l2;
    }
    __syncthreads();

    // ---- load this warp's W fragments into registers (persist all levels) ----
    uint32_t Ah[16][4], Al[16][4];
    {
        const int g = lane >> 3, lr = lane & 7;
        const int row = wq * 16 + lr + (g & 1) * 8;
#pragma unroll
        for (int kt = 0; kt < 16; kt++) {
            int kb = kt * 32 + (g >> 1) * 16;
            uint32_t off = (uint32_t)((kb >> 7) * W_CS)
                         + sw128((uint32_t)(row * 128 + (kb & 127)));
            ldsm4(sb + OFF_W + off, Ah[kt][0], Ah[kt][1], Ah[kt][2], Ah[kt][3]);
            ldsm4(sb + OFF_W + 4 * W_CS + off, Al[kt][0], Al[kt][1], Al[kt][2], Al[kt][3]);
        }
    }
    const float bias0 = b_tree[wq * 16 + (lane >> 2)];
    const float bias1 = b_tree[wq * 16 + (lane >> 2) + 8];
    float* rootp = (float*)(sm + OFF_ROOT);

    run_level<8, 64, false>(sm, sb, OFF_B0, B0_CS, OFF_B1, B1_CS, Ah, Al, bias0, bias1, wq, lane, rootp);
    __syncthreads();
    run_level<4, 32, false>(sm, sb, OFF_B1, B1_CS, OFF_B0, B0_CS, Ah, Al, bias0, bias1, wq, lane, rootp);
    __syncthreads();
    run_level<2, 16, false>(sm, sb, OFF_B0, B0_CS, OFF_B1, B1_CS, Ah, Al, bias0, bias1, wq, lane, rootp);
    __syncthreads();
    run_level<1, 8, false>(sm, sb, OFF_B1, B1_CS, OFF_B0, B0_CS, Ah, Al, bias0, bias1, wq, lane, rootp);
    __syncthreads();
    run_level<1, 4, false>(sm, sb, OFF_B0, B0_CS, OFF_B1, B1_CS, Ah, Al, bias0, bias1, wq, lane, rootp);
    __syncthreads();
    run_level<1, 2, false>(sm, sb, OFF_B1, B1_CS, OFF_B0, B0_CS, Ah, Al, bias0, bias1, wq, lane, rootp);
    __syncthreads();
    run_level<1, 1, true >(sm, sb, OFF_B0, B0_CS, OFF_B1, B1_CS, Ah, Al, bias0, bias1, wq, lane, rootp);
    __syncthreads();

    // ---- classifier on fp32 root ----
    if (tid < 96) {
        int o = tid >> 5, l2 = tid & 31;
        float p = 0.f;
#pragma unroll
        for (int k = 0; k < 4; k++) {
            int ee = l2 + 32 * k;
            p += rootp[ee] * W_cls[o * EE + ee];
        }
#pragma unroll
        for (int off = 16; off; off >>= 1)
            p += __shfl_down_sync(0xffffffffu, p, off);
        if (l2 == 0) out[b * NOUTC + o] = p + b_cls[o];
    }
}

extern "C" void kernel_launch(void* const* d_in, const int* in_sizes, int n_in,
                              void* d_out, int out_size)
{
    const void*  tokens = d_in[0];
    const float* emb    = (const float*)d_in[1];
    const float* W_tree = (const float*)d_in[2];
    const float* b_tree = (const float*)d_in[3];
    const float* W_cls  = (const float*)d_in[4];
    const float* b_cls  = (const float*)d_in[5];
    float* out = (float*)d_out;

    cudaFuncSetAttribute(tree_kernel,
                         cudaFuncAttributeMaxDynamicSharedMemorySize, SMEM_BYTES);

    detect_tok_kernel<<<1, 256>>>((const unsigned int*)tokens);
    tree_kernel<<<NB, 256, SMEM_BYTES>>>(tokens, emb, W_tree, b_tree,
                                         W_cls, b_cls, out);
}

// round 8
// speedup vs baseline: 3.2903x; 1.2461x over previous
#include <cuda_runtime.h>
#include <cuda_bf16.h>
#include <stdint.h>

#define NB   4096
#define NOUTC 3

// ---- shared memory (bytes): ROOT(2x128 f32) | B0: 128 rows | B1: 64 rows ----
// Row = 256 bf16 (512B) split: hi 4 chunks x [rows x 128B] then lo 4 chunks.
#define OFF_ROOT 0
#define OFF_B0   1024
#define B0_CS    16384                      // 128 rows * 128B per chunk
#define OFF_B1   (OFF_B0 + 8 * B0_CS)       // 132096
#define B1_CS    8192                       // 64 rows * 128B
#define SMEM_BYTES (OFF_B1 + 8 * B1_CS)     // 197632

__device__ int g_tok_is_i32;

__global__ void detect_tok_kernel(const unsigned int* __restrict__ w) {
    __shared__ int s;
    if (threadIdx.x == 0) s = 0;
    __syncthreads();
    int any = 0;
    for (int i = threadIdx.x; i < 2048; i += 256)
        any |= (w[2 * i + 1] != 0u);
    if (any) atomicOr(&s, 1);
    __syncthreads();
    if (threadIdx.x == 0) g_tok_is_i32 = s;
}

static __device__ __forceinline__ uint32_t sw128(uint32_t b) {
    return b ^ ((b >> 3) & 0x70);
}
static __device__ __forceinline__ uint32_t smem_u32(const void* p) {
    uint32_t a;
    asm("{ .reg .u64 t; cvta.to.shared.u64 t, %1; cvt.u32.u64 %0, t; }" : "=r"(a) : "l"(p));
    return a;
}
static __device__ __forceinline__ void ldsm4(uint32_t addr, uint32_t& r0, uint32_t& r1,
                                             uint32_t& r2, uint32_t& r3) {
    asm volatile("ldmatrix.sync.aligned.m8n8.x4.shared.b16 {%0,%1,%2,%3}, [%4];"
                 : "=r"(r0), "=r"(r1), "=r"(r2), "=r"(r3) : "r"(addr));
}
static __device__ __forceinline__ void mma_bf16(float& d0, float& d1, float& d2, float& d3,
                                                const uint32_t a[4], uint32_t b0, uint32_t b1) {
    asm volatile("mma.sync.aligned.m16n8k16.row.col.f32.bf16.bf16.f32 "
                 "{%0,%1,%2,%3}, {%4,%5,%6,%7}, {%8,%9}, {%0,%1,%2,%3};"
                 : "+f"(d0), "+f"(d1), "+f"(d2), "+f"(d3)
                 : "r"(a[0]), "r"(a[1]), "r"(a[2]), "r"(a[3]), "r"(b0), "r"(b1));
}
static __device__ __forceinline__ float tanh_fast(float x) {
    float t = __expf(2.0f * x);
    return 1.0f - __fdividef(2.0f, t + 1.0f);
}
static __device__ __forceinline__ uint32_t pack_hi(float x, float y) {
    __nv_bfloat16 h0 = __float2bfloat16(x), h1 = __float2bfloat16(y);
    return ((uint32_t)*(uint16_t*)&h1 << 16) | *(uint16_t*)&h0;
}
static __device__ __forceinline__ uint32_t pack_lo(float x, float y, uint32_t hi) {
    uint16_t u0 = (uint16_t)hi, u1 = (uint16_t)(hi >> 16);
    __nv_bfloat16 h0 = *(__nv_bfloat16*)&u0, h1 = *(__nv_bfloat16*)&u1;
    __nv_bfloat16 l0 = __float2bfloat16(x - __bfloat162float(h0));
    __nv_bfloat16 l1 = __float2bfloat16(y - __bfloat162float(h1));
    return ((uint32_t)*(uint16_t*)&l1 << 16) | *(uint16_t*)&l0;
}
static __device__ __forceinline__ void store_out(char* sm, uint32_t dstHi, uint32_t dcs,
                                                 int r, int k, float x) {
    __nv_bfloat16 h = __float2bfloat16(x);
    __nv_bfloat16 l = __float2bfloat16(x - __bfloat162float(h));
    int chunk = k >> 6;
    uint32_t off = sw128((uint32_t)(r * 128 + (k & 63) * 2));
    *(__nv_bfloat16*)(sm + dstHi + (uint32_t)chunk * dcs + off) = h;
    *(__nv_bfloat16*)(sm + dstHi + 4u * dcs + (uint32_t)chunk * dcs + off) = l;
}

// One level over 2 trees. Src rows: tree t occupies [t*SPT, (t+1)*SPT).
// Output node n (== src row n): tree t=n/SPT, local ln=n%SPT ->
// dst row t*(SPT/2)+(ln>>1), k=(ln&1)*128+e.
template<int NTILES, int SPT, bool LAST>
static __device__ __forceinline__ void run_level(
    char* sm, uint32_t sb, uint32_t srcHi, uint32_t scs, uint32_t dstHi, uint32_t dcs,
    const uint32_t Ah[16][4], const uint32_t Al[16][4],
    float bias0, float bias1, int wq, int lane, float* rootp)
{
    const int g = lane >> 3, lr = lane & 7;
#pragma unroll 1
    for (int nb = 0; nb < NTILES; nb++) {
        uint32_t Bh[16][2], Bl[16][2];
        const int row = nb * 8 + lr;
#pragma unroll
        for (int j = 0; j < 8; j++) {
            int kb = j * 64 + g * 16;
            uint32_t off = (uint32_t)((kb >> 7) * scs)
                         + sw128((uint32_t)(row * 128 + (kb & 127)));
            ldsm4(sb + srcHi + off,
                  Bh[2 * j][0], Bh[2 * j][1], Bh[2 * j + 1][0], Bh[2 * j + 1][1]);
        }
#pragma unroll
        for (int j = 0; j < 8; j++) {
            int kb = j * 64 + g * 16;
            uint32_t off = (uint32_t)((kb >> 7) * scs)
                         + sw128((uint32_t)(row * 128 + (kb & 127)));
            ldsm4(sb + srcHi + 4u * scs + off,
                  Bl[2 * j][0], Bl[2 * j][1], Bl[2 * j + 1][0], Bl[2 * j + 1][1]);
        }

        float c10 = 0.f, c11 = 0.f, c12 = 0.f, c13 = 0.f;   // Ah*Bh
        float c20 = 0.f, c21 = 0.f, c22 = 0.f, c23 = 0.f;   // Al*Bh
        float c30 = 0.f, c31 = 0.f, c32 = 0.f, c33 = 0.f;   // Ah*Bl
#pragma unroll
        for (int kt = 0; kt < 16; kt++) {
            mma_bf16(c10, c11, c12, c13, Ah[kt], Bh[kt][0], Bh[kt][1]);
            mma_bf16(c20, c21, c22, c23, Al[kt], Bh[kt][0], Bh[kt][1]);
            mma_bf16(c30, c31, c32, c33, Ah[kt], Bl[kt][0], Bl[kt][1]);
        }
        float d0 = (bias0 + c10) + (c20 + c30);
        float d1 = (bias0 + c11) + (c21 + c31);
        float d2 = (bias1 + c12) + (c22 + c32);
        float d3 = (bias1 + c13) + (c23 + c33);

        const int e0 = wq * 16 + (lane >> 2);
        const int nL = nb * 8 + 2 * (lane & 3);
        if constexpr (!LAST) {
            if (nL < 2 * SPT) {
                int t0 = nL / SPT, ln0 = nL % SPT;
                int r0 = t0 * (SPT / 2) + (ln0 >> 1), k0 = (ln0 & 1) * 128;
                store_out(sm, dstHi, dcs, r0, k0 + e0,     tanh_fast(d0));
                store_out(sm, dstHi, dcs, r0, k0 + e0 + 8, tanh_fast(d2));
                int n1 = nL + 1, t1 = n1 / SPT, ln1 = n1 % SPT;
                int r1 = t1 * (SPT / 2) + (ln1 >> 1), k1 = (ln1 & 1) * 128;
                store_out(sm, dstHi, dcs, r1, k1 + e0,     tanh_fast(d1));
                store_out(sm, dstHi, dcs, r1, k1 + e0 + 8, tanh_fast(d3));
            }
        } else {
            if ((lane & 3) == 0) {           // nL==0: d0/d2 -> tree0, d1/d3 -> tree1
                rootp[e0]           = tanh_fast(d0);
                rootp[e0 + 8]       = tanh_fast(d2);
                rootp[128 + e0]     = tanh_fast(d1);
                rootp[128 + e0 + 8] = tanh_fast(d3);
            }
        }
    }
}

__global__ __launch_bounds__(256, 1)
void tree_kernel(const void* __restrict__ tokens_raw,
                 const float* __restrict__ emb,
                 const float* __restrict__ W_tree,
                 const float* __restrict__ b_tree,
                 const float* __restrict__ W_cls,
                 const float* __restrict__ b_cls,
                 float* __restrict__ out)
{
    extern __shared__ char sm[];
    const uint32_t sb = smem_u32(sm);
    const int tid = threadIdx.x, wq = tid >> 5, lane = tid & 31;
    const int b = blockIdx.x;                 // handles trees 2b, 2b+1

    // ---- leaf gather for both trees -> B0 (128 rows) ----
    const int is32 = g_tok_is_i32;
    const long long* t64 = (const long long*)tokens_raw;
    const int*       t32 = (const int*)tokens_raw;
    for (int idx = tid; idx < 256 * 32; idx += 256) {
        int l = idx >> 5, q = idx & 31;               // leaf 0..255, f4-col
        long long tok = is32 ? (long long)t32[b * 256 + l] : t64[b * 256 + l];
        float4 v = ((const float4*)emb)[tok * 32 + q];
        int t = l >> 7, ll = l & 127;
        int row = t * 64 + (ll >> 1);
        int kb16 = ((ll & 1) << 7) + q * 4;           // k element index
        int chunk = kb16 >> 6, inner = kb16 & 63;
        uint32_t off = sw128((uint32_t)(row * 128 + inner * 2));
        char* hiT = sm + OFF_B0 + chunk * B0_CS;
        char* loT = hiT + 4 * B0_CS;
        uint32_t p0 = pack_hi(v.x, v.y), p1 = pack_hi(v.z, v.w);
        *(uint32_t*)(hiT + off)     = p0;
        *(uint32_t*)(hiT + off + 4) = p1;
        *(uint32_t*)(loT + off)     = pack_lo(v.x, v.y, p0);
        *(uint32_t*)(loT + off + 4) = pack_lo(v.z, v.w, p1);
    }

    // ---- W fragments straight from global (m16n8k16 A-lane mapping) ----
    uint32_t Ah[16][4], Al[16][4];
    {
        const int r0 = wq * 16 + (lane >> 2);
        const int c0 = (lane & 3) * 2;
#pragma unroll
        for (int kt = 0; kt < 16; kt++) {
            int k0 = kt * 16 + c0;
            float2 w00 = *(const float2*)(W_tree + r0 * 256 + k0);
            float2 w10 = *(const float2*)(W_tree + (r0 + 8) * 256 + k0);
            float2 w01 = *(const float2*)(W_tree + r0 * 256 + k0 + 8);
            float2 w11 = *(const float2*)(W_tree + (r0 + 8) * 256 + k0 + 8);
            Ah[kt][0] = pack_hi(w00.x, w00.y); Al[kt][0] = pack_lo(w00.x, w00.y, Ah[kt][0]);
            Ah[kt][1] = pack_hi(w10.x, w10.y); Al[kt][1] = pack_lo(w10.x, w10.y, Ah[kt][1]);
            Ah[kt][2] = pack_hi(w01.x, w01.y); Al[kt][2] = pack_lo(w01.x, w01.y, Ah[kt][2]);
            Ah[kt][3] = pack_hi(w11.x, w11.y); Al[kt][3] = pack_lo(w11.x, w11.y, Ah[kt][3]);
        }
    }
    const float bias0 = b_tree[wq * 16 + (lane >> 2)];
    const float bias1 = b_tree[wq * 16 + (lane >> 2) + 8];
    float* rootp = (float*)(sm + OFF_ROOT);
    __syncthreads();

    //          NTILES SPT LAST        src            dst
    run_level<16, 64, false>(sm, sb, OFF_B0, B0_CS, OFF_B1, B1_CS, Ah, Al, bias0, bias1, wq, lane, rootp);
    __syncthreads();
    run_level< 8, 32, false>(sm, sb, OFF_B1, B1_CS, OFF_B0, B0_CS, Ah, Al, bias0, bias1, wq, lane, rootp);
    __syncthreads();
    run_level< 4, 16, false>(sm, sb, OFF_B0, B0_CS, OFF_B1, B1_CS, Ah, Al, bias0, bias1, wq, lane, rootp);
    __syncthreads();
    run_level< 2,  8, false>(sm, sb, OFF_B1, B1_CS, OFF_B0, B0_CS, Ah, Al, bias0, bias1, wq, lane, rootp);
    __syncthreads();
    run_level< 1,  4, false>(sm, sb, OFF_B0, B0_CS, OFF_B1, B1_CS, Ah, Al, bias0, bias1, wq, lane, rootp);
    __syncthreads();
    run_level< 1,  2, false>(sm, sb, OFF_B1, B1_CS, OFF_B0, B0_CS, Ah, Al, bias0, bias1, wq, lane, rootp);
    __syncthreads();
    run_level< 1,  1, true >(sm, sb, OFF_B0, B0_CS, OFF_B1, B1_CS, Ah, Al, bias0, bias1, wq, lane, rootp);
    __syncthreads();

    // ---- classifier for both trees (6 warp-dots) ----
    if (tid < 192) {
        int w = tid >> 5;                 // 0..5
        int t = (w >= 3) ? 1 : 0, o = w - t * 3;
        float p = 0.f;
#pragma unroll
        for (int k = 0; k < 4; k++) {
            int ee = lane + 32 * k;
            p += rootp[t * 128 + ee] * W_cls[o * 128 + ee];
        }
#pragma unroll
        for (int off = 16; off; off >>= 1)
            p += __shfl_down_sync(0xffffffffu, p, off);
        if (lane == 0) out[(2 * b + t) * NOUTC + o] = p + b_cls[o];
    }
}

extern "C" void kernel_launch(void* const* d_in, const int* in_sizes, int n_in,
                              void* d_out, int out_size)
{
    const void*  tokens = d_in[0];
    const float* emb    = (const float*)d_in[1];
    const float* W_tree = (const float*)d_in[2];
    const float* b_tree = (const float*)d_in[3];
    const float* W_cls  = (const float*)d_in[4];
    const float* b_cls  = (const float*)d_in[5];
    float* out = (float*)d_out;

    cudaFuncSetAttribute(tree_kernel,
                         cudaFuncAttributeMaxDynamicSharedMemorySize, SMEM_BYTES);

    detect_tok_kernel<<<1, 256>>>((const unsigned int*)tokens);
    tree_kernel<<<NB / 2, 256, SMEM_BYTES>>>(tokens, emb, W_tree, b_tree,
                                             W_cls, b_cls, out);
}

// round 9
// speedup vs baseline: 4.2292x; 1.2854x over previous
#include <cuda_runtime.h>
#include <cuda_bf16.h>
#include <stdint.h>

#define NB   4096
#define NOUTC 3

// ---- shared memory (bytes): ROOT(2x128 f32) | B0: 128 rows | B1: 64 rows ----
#define OFF_ROOT 0
#define OFF_B0   1024
#define B0_CS    16384
#define OFF_B1   (OFF_B0 + 8 * B0_CS)       // 132096
#define B1_CS    8192
#define SMEM_BYTES (OFF_B1 + 8 * B1_CS)     // 197632

__device__ int g_tok_is_i32;

__global__ void detect_tok_kernel(const unsigned int* __restrict__ w) {
    __shared__ int s;
    if (threadIdx.x == 0) s = 0;
    __syncthreads();
    int any = 0;
    for (int i = threadIdx.x; i < 2048; i += 256)
        any |= (w[2 * i + 1] != 0u);
    if (any) atomicOr(&s, 1);
    __syncthreads();
    if (threadIdx.x == 0) g_tok_is_i32 = s;
}

static __device__ __forceinline__ uint32_t sw128(uint32_t b) {
    return b ^ ((b >> 3) & 0x70);
}
static __device__ __forceinline__ uint32_t smem_u32(const void* p) {
    uint32_t a;
    asm("{ .reg .u64 t; cvta.to.shared.u64 t, %1; cvt.u32.u64 %0, t; }" : "=r"(a) : "l"(p));
    return a;
}
static __device__ __forceinline__ void ldsm4(uint32_t addr, uint32_t& r0, uint32_t& r1,
                                             uint32_t& r2, uint32_t& r3) {
    asm volatile("ldmatrix.sync.aligned.m8n8.x4.shared.b16 {%0,%1,%2,%3}, [%4];"
                 : "=r"(r0), "=r"(r1), "=r"(r2), "=r"(r3) : "r"(addr));
}
static __device__ __forceinline__ void mma_bf16(float& d0, float& d1, float& d2, float& d3,
                                                const uint32_t a[4], uint32_t b0, uint32_t b1) {
    asm volatile("mma.sync.aligned.m16n8k16.row.col.f32.bf16.bf16.f32 "
                 "{%0,%1,%2,%3}, {%4,%5,%6,%7}, {%8,%9}, {%0,%1,%2,%3};"
                 : "+f"(d0), "+f"(d1), "+f"(d2), "+f"(d3)
                 : "r"(a[0]), "r"(a[1]), "r"(a[2]), "r"(a[3]), "r"(b0), "r"(b1));
}
static __device__ __forceinline__ float tanh_fast(float x) {
    float t = __expf(2.0f * x);
    return 1.0f - __fdividef(2.0f, t + 1.0f);
}
static __device__ __forceinline__ uint32_t pack_hi(float x, float y) {
    __nv_bfloat16 h0 = __float2bfloat16(x), h1 = __float2bfloat16(y);
    return ((uint32_t)*(uint16_t*)&h1 << 16) | *(uint16_t*)&h0;
}
static __device__ __forceinline__ uint32_t pack_lo(float x, float y, uint32_t hi) {
    uint16_t u0 = (uint16_t)hi, u1 = (uint16_t)(hi >> 16);
    __nv_bfloat16 h0 = *(__nv_bfloat16*)&u0, h1 = *(__nv_bfloat16*)&u1;
    __nv_bfloat16 l0 = __float2bfloat16(x - __bfloat162float(h0));
    __nv_bfloat16 l1 = __float2bfloat16(y - __bfloat162float(h1));
    return ((uint32_t)*(uint16_t*)&l1 << 16) | *(uint16_t*)&l0;
}
static __device__ __forceinline__ void store_out(char* sm, uint32_t dstHi, uint32_t dcs,
                                                 int r, int k, float x) {
    __nv_bfloat16 h = __float2bfloat16(x);
    __nv_bfloat16 l = __float2bfloat16(x - __bfloat162float(h));
    int chunk = k >> 6;
    uint32_t off = sw128((uint32_t)(r * 128 + (k & 63) * 2));
    *(__nv_bfloat16*)(sm + dstHi + (uint32_t)chunk * dcs + off) = h;
    *(__nv_bfloat16*)(sm + dstHi + 4u * dcs + (uint32_t)chunk * dcs + off) = l;
}

// One level over 2 trees; pipelined: MMAs -> prefetch next tile's B -> epilogue.
template<int NTILES, int SPT, bool LAST>
static __device__ __forceinline__ void run_level(
    char* sm, uint32_t sb, uint32_t srcHi, uint32_t scs, uint32_t dstHi, uint32_t dcs,
    const uint32_t Ah[16][4], const uint32_t Al[16][4],
    float bias0, float bias1, int wq, int lane, float* rootp)
{
    const int g = lane >> 3, lr = lane & 7;
    uint32_t Bh[16][2], Bl[16][2];

    // prologue: load tile 0
    {
        const int row = lr;
#pragma unroll
        for (int j = 0; j < 8; j++) {
            int kb = j * 64 + g * 16;
            uint32_t off = (uint32_t)((kb >> 7) * scs)
                         + sw128((uint32_t)(row * 128 + (kb & 127)));
            ldsm4(sb + srcHi + off,
                  Bh[2 * j][0], Bh[2 * j][1], Bh[2 * j + 1][0], Bh[2 * j + 1][1]);
        }
#pragma unroll
        for (int j = 0; j < 8; j++) {
            int kb = j * 64 + g * 16;
            uint32_t off = (uint32_t)((kb >> 7) * scs)
                         + sw128((uint32_t)(row * 128 + (kb & 127)));
            ldsm4(sb + srcHi + 4u * scs + off,
                  Bl[2 * j][0], Bl[2 * j][1], Bl[2 * j + 1][0], Bl[2 * j + 1][1]);
        }
    }

#pragma unroll 1
    for (int nb = 0; nb < NTILES; nb++) {
        // 6 independent accumulation chains (each term split even/odd kt)
        float c[6][4];
#pragma unroll
        for (int i = 0; i < 6; i++) {
            c[i][0] = 0.f; c[i][1] = 0.f; c[i][2] = 0.f; c[i][3] = 0.f;
        }
#pragma unroll
        for (int kt = 0; kt < 16; kt++) {
            const int a = kt & 1;
            mma_bf16(c[a][0], c[a][1], c[a][2], c[a][3],         Ah[kt], Bh[kt][0], Bh[kt][1]);
            mma_bf16(c[2 + a][0], c[2 + a][1], c[2 + a][2], c[2 + a][3], Al[kt], Bh[kt][0], Bh[kt][1]);
            mma_bf16(c[4 + a][0], c[4 + a][1], c[4 + a][2], c[4 + a][3], Ah[kt], Bl[kt][0], Bl[kt][1]);
        }

        // prefetch next tile's B (WAR-safe: all reads issued) before epilogue
        if (nb + 1 < NTILES) {
            const int row = (nb + 1) * 8 + lr;
#pragma unroll
            for (int j = 0; j < 8; j++) {
                int kb = j * 64 + g * 16;
                uint32_t off = (uint32_t)((kb >> 7) * scs)
                             + sw128((uint32_t)(row * 128 + (kb & 127)));
                ldsm4(sb + srcHi + off,
                      Bh[2 * j][0], Bh[2 * j][1], Bh[2 * j + 1][0], Bh[2 * j + 1][1]);
            }
#pragma unroll
            for (int j = 0; j < 8; j++) {
                int kb = j * 64 + g * 16;
                uint32_t off = (uint32_t)((kb >> 7) * scs)
                             + sw128((uint32_t)(row * 128 + (kb & 127)));
                ldsm4(sb + srcHi + 4u * scs + off,
                      Bl[2 * j][0], Bl[2 * j][1], Bl[2 * j + 1][0], Bl[2 * j + 1][1]);
            }
        }

        // epilogue (overlaps prefetch latency)
        float d0 = bias0 + ((c[0][0] + c[1][0]) + (c[2][0] + c[3][0]) + (c[4][0] + c[5][0]));
        float d1 = bias0 + ((c[0][1] + c[1][1]) + (c[2][1] + c[3][1]) + (c[4][1] + c[5][1]));
        float d2 = bias1 + ((c[0][2] + c[1][2]) + (c[2][2] + c[3][2]) + (c[4][2] + c[5][2]));
        float d3 = bias1 + ((c[0][3] + c[1][3]) + (c[2][3] + c[3][3]) + (c[4][3] + c[5][3]));

        const int e0 = wq * 16 + (lane >> 2);
        const int nL = nb * 8 + 2 * (lane & 3);
        if constexpr (!LAST) {
            if (nL < 2 * SPT) {
                float t0v = tanh_fast(d0), t1v = tanh_fast(d1);
                float t2v = tanh_fast(d2), t3v = tanh_fast(d3);
                int t0 = nL / SPT, ln0 = nL % SPT;
                int r0 = t0 * (SPT / 2) + (ln0 >> 1), k0 = (ln0 & 1) * 128;
                store_out(sm, dstHi, dcs, r0, k0 + e0,     t0v);
                store_out(sm, dstHi, dcs, r0, k0 + e0 + 8, t2v);
                int n1 = nL + 1, t1 = n1 / SPT, ln1 = n1 % SPT;
                int r1 = t1 * (SPT / 2) + (ln1 >> 1), k1 = (ln1 & 1) * 128;
                store_out(sm, dstHi, dcs, r1, k1 + e0,     t1v);
                store_out(sm, dstHi, dcs, r1, k1 + e0 + 8, t3v);
            }
        } else {
            if ((lane & 3) == 0) {
                rootp[e0]           = tanh_fast(d0);
                rootp[e0 + 8]       = tanh_fast(d2);
                rootp[128 + e0]     = tanh_fast(d1);
                rootp[128 + e0 + 8] = tanh_fast(d3);
            }
        }
    }
}

__global__ __launch_bounds__(256, 1)
void tree_kernel(const void* __restrict__ tokens_raw,
                 const float* __restrict__ emb,
                 const float* __restrict__ W_tree,
                 const float* __restrict__ b_tree,
                 const float* __restrict__ W_cls,
                 const float* __restrict__ b_cls,
                 float* __restrict__ out)
{
    extern __shared__ char sm[];
    const uint32_t sb = smem_u32(sm);
    const int tid = threadIdx.x, wq = tid >> 5, lane = tid & 31;
    const int b = blockIdx.x;                 // trees 2b, 2b+1

    // ---- leaf gather, MLP-8 batched: 1 token LDG/thread + shfl broadcast ----
    const int is32 = g_tok_is_i32;
    {
        const long long* t64 = (const long long*)tokens_raw;
        const int*       t32 = (const int*)tokens_raw;
        const int myLeaf = wq + 8 * lane;         // unique 0..255
        int myTok = is32 ? t32[b * 256 + myLeaf]
                         : (int)t64[b * 256 + myLeaf];
#pragma unroll
        for (int grp = 0; grp < 4; grp++) {
            float4 v[8];
#pragma unroll
            for (int j = 0; j < 8; j++) {
                int i = grp * 8 + j;              // leaf wq + 8*i
                int tk = __shfl_sync(0xffffffffu, myTok, i);
                v[j] = ((const float4*)emb)[(long long)tk * 32 + lane];
            }
#pragma unroll
            for (int j = 0; j < 8; j++) {
                int i = grp * 8 + j;
                int l = wq + 8 * i;
                int t = l >> 7, ll = l & 127;
                int row = t * 64 + (ll >> 1);
                int kb16 = ((ll & 1) << 7) + lane * 4;
                int chunk = kb16 >> 6, inner = kb16 & 63;
                uint32_t off = sw128((uint32_t)(row * 128 + inner * 2));
                char* hiT = sm + OFF_B0 + chunk * B0_CS;
                char* loT = hiT + 4 * B0_CS;
                uint32_t p0 = pack_hi(v[j].x, v[j].y), p1 = pack_hi(v[j].z, v[j].w);
                *(uint32_t*)(hiT + off)     = p0;
                *(uint32_t*)(hiT + off + 4) = p1;
                *(uint32_t*)(loT + off)     = pack_lo(v[j].x, v[j].y, p0);
                *(uint32_t*)(loT + off + 4) = pack_lo(v[j].z, v[j].w, p1);
            }
        }
    }

    // ---- W fragments straight from global (m16n8k16 A-lane mapping) ----
    uint32_t Ah[16][4], Al[16][4];
    {
        const int r0 = wq * 16 + (lane >> 2);
        const int c0 = (lane & 3) * 2;
#pragma unroll
        for (int kt = 0; kt < 16; kt++) {
            int k0 = kt * 16 + c0;
            float2 w00 = *(const float2*)(W_tree + r0 * 256 + k0);
            float2 w10 = *(const float2*)(W_tree + (r0 + 8) * 256 + k0);
            float2 w01 = *(const float2*)(W_tree + r0 * 256 + k0 + 8);
            float2 w11 = *(const float2*)(W_tree + (r0 + 8) * 256 + k0 + 8);
            Ah[kt][0] = pack_hi(w00.x, w00.y); Al[kt][0] = pack_lo(w00.x, w00.y, Ah[kt][0]);
            Ah[kt][1] = pack_hi(w10.x, w10.y); Al[kt][1] = pack_lo(w10.x, w10.y, Ah[kt][1]);
            Ah[kt][2] = pack_hi(w01.x, w01.y); Al[kt][2] = pack_lo(w01.x, w01.y, Ah[kt][2]);
            Ah[kt][3] = pack_hi(w11.x, w11.y); Al[kt][3] = pack_lo(w11.x, w11.y, Ah[kt][3]);
        }
    }
    const float bias0 = b_tree[wq * 16 + (lane >> 2)];
    const float bias1 = b_tree[wq * 16 + (lane >> 2) + 8];
    float* rootp = (float*)(sm + OFF_ROOT);
    __syncthreads();

    run_level<16, 64, false>(sm, sb, OFF_B0, B0_CS, OFF_B1, B1_CS, Ah, Al, bias0, bias1, wq, lane, rootp);
    __syncthreads();
    run_level< 8, 32, false>(sm, sb, OFF_B1, B1_CS, OFF_B0, B0_CS, Ah, Al, bias0, bias1, wq, lane, rootp);
    __syncthreads();
    run_level< 4, 16, false>(sm, sb, OFF_B0, B0_CS, OFF_B1, B1_CS, Ah, Al, bias0, bias1, wq, lane, rootp);
    __syncthreads();
    run_level< 2,  8, false>(sm, sb, OFF_B1, B1_CS, OFF_B0, B0_CS, Ah, Al, bias0, bias1, wq, lane, rootp);
    __syncthreads();
    run_level< 1,  4, false>(sm, sb, OFF_B0, B0_CS, OFF_B1, B1_CS, Ah, Al, bias0, bias1, wq, lane, rootp);
    __syncthreads();
    run_level< 1,  2, false>(sm, sb, OFF_B1, B1_CS, OFF_B0, B0_CS, Ah, Al, bias0, bias1, wq, lane, rootp);
    __syncthreads();
    run_level< 1,  1, true >(sm, sb, OFF_B0, B0_CS, OFF_B1, B1_CS, Ah, Al, bias0, bias1, wq, lane, rootp);
    __syncthreads();

    // ---- classifier for both trees (6 warp-dots) ----
    if (tid < 192) {
        int w = tid >> 5;
        int t = (w >= 3) ? 1 : 0, o = w - t * 3;
        float p = 0.f;
#pragma unroll
        for (int k = 0; k < 4; k++) {
            int ee = lane + 32 * k;
            p += rootp[t * 128 + ee] * W_cls[o * 128 + ee];
        }
#pragma unroll
        for (int off = 16; off; off >>= 1)
            p += __shfl_down_sync(0xffffffffu, p, off);
        if (lane == 0) out[(2 * b + t) * NOUTC + o] = p + b_cls[o];
    }
}

extern "C" void kernel_launch(void* const* d_in, const int* in_sizes, int n_in,
                              void* d_out, int out_size)
{
    const void*  tokens = d_in[0];
    const float* emb    = (const float*)d_in[1];
    const float* W_tree = (const float*)d_in[2];
    const float* b_tree = (const float*)d_in[3];
    const float* W_cls  = (const float*)d_in[4];
    const float* b_cls  = (const float*)d_in[5];
    float* out = (float*)d_out;

    cudaFuncSetAttribute(tree_kernel,
                         cudaFuncAttributeMaxDynamicSharedMemorySize, SMEM_BYTES);

    detect_tok_kernel<<<1, 256>>>((const unsigned int*)tokens);
    tree_kernel<<<NB / 2, 256, SMEM_BYTES>>>(tokens, emb, W_tree, b_tree,
                                             W_cls, b_cls, out);
}

// round 11
// speedup vs baseline: 9.1978x; 2.1749x over previous
#include <cuda_runtime.h>
#include <cuda_fp16.h>
#include <stdint.h>

#define NB   4096
#define NOUTC 3

// ---- shared memory (bytes): ROOT(2x128 f32) | B0: 128 rows | B1: 64 rows ----
// Row = 256 fp16 (512B) as 4 sw128 chunks x [rows x 128B]. Single tier (no lo).
#define OFF_ROOT 0
#define OFF_B0   1024
#define B0_CS    16384
#define OFF_B1   (OFF_B0 + 4 * B0_CS)       // 66560
#define B1_CS    8192
#define SMEM_BYTES (OFF_B1 + 4 * B1_CS)     // 99328  (<=113KB -> 2 CTAs/SM)

__device__ int g_tok_is_i32;

__global__ void detect_tok_kernel(const unsigned int* __restrict__ w) {
    __shared__ int s;
    if (threadIdx.x == 0) s = 0;
    __syncthreads();
    int any = 0;
    for (int i = threadIdx.x; i < 2048; i += 256)
        any |= (w[2 * i + 1] != 0u);
    if (any) atomicOr(&s, 1);
    __syncthreads();
    if (threadIdx.x == 0) g_tok_is_i32 = s;
}

static __device__ __forceinline__ uint32_t sw128(uint32_t b) {
    return b ^ ((b >> 3) & 0x70);
}
static __device__ __forceinline__ uint32_t smem_u32(const void* p) {
    uint32_t a;
    asm("{ .reg .u64 t; cvta.to.shared.u64 t, %1; cvt.u32.u64 %0, t; }" : "=r"(a) : "l"(p));
    return a;
}
static __device__ __forceinline__ void ldsm4(uint32_t addr, uint32_t& r0, uint32_t& r1,
                                             uint32_t& r2, uint32_t& r3) {
    asm volatile("ldmatrix.sync.aligned.m8n8.x4.shared.b16 {%0,%1,%2,%3}, [%4];"
                 : "=r"(r0), "=r"(r1), "=r"(r2), "=r"(r3) : "r"(addr));
}
static __device__ __forceinline__ void mma_f16(float& d0, float& d1, float& d2, float& d3,
                                               const uint32_t a[4], uint32_t b0, uint32_t b1) {
    asm volatile("mma.sync.aligned.m16n8k16.row.col.f32.f16.f16.f32 "
                 "{%0,%1,%2,%3}, {%4,%5,%6,%7}, {%8,%9}, {%0,%1,%2,%3};"
                 : "+f"(d0), "+f"(d1), "+f"(d2), "+f"(d3)
                 : "r"(a[0]), "r"(a[1]), "r"(a[2]), "r"(a[3]), "r"(b0), "r"(b1));
}
static __device__ __forceinline__ float tanh_fast(float x) {
    float t = __expf(2.0f * x);
    return 1.0f - __fdividef(2.0f, t + 1.0f);
}
static __device__ __forceinline__ uint32_t pack_h2(float x, float y) {
    __half h0 = __float2half_rn(x), h1 = __float2half_rn(y);
    return ((uint32_t)*(uint16_t*)&h1 << 16) | *(uint16_t*)&h0;
}
static __device__ __forceinline__ void store_out(char* sm, uint32_t dstHi, uint32_t dcs,
                                                 int r, int k, float x) {
    __half h = __float2half_rn(x);
    int chunk = k >> 6;
    uint32_t off = sw128((uint32_t)(r * 128 + (k & 63) * 2));
    *(__half*)(sm + dstHi + (uint32_t)chunk * dcs + off) = h;
}

// One level over 2 trees; pipelined: MMAs -> prefetch next tile's B -> epilogue.
template<int NTILES, int SPT, bool LAST>
static __device__ __forceinline__ void run_level(
    char* sm, uint32_t sb, uint32_t srcHi, uint32_t scs, uint32_t dstHi, uint32_t dcs,
    const uint32_t A[16][4],
    float bias0, float bias1, int wq, int lane, float* rootp)
{
    const int g = lane >> 3, lr = lane & 7;
    uint32_t Bh[16][2];

    // prologue: load tile 0
    {
        const int row = lr;
#pragma unroll
        for (int j = 0; j < 8; j++) {
            int kb = j * 64 + g * 16;
            uint32_t off = (uint32_t)((kb >> 7) * scs)
                         + sw128((uint32_t)(row * 128 + (kb & 127)));
            ldsm4(sb + srcHi + off,
                  Bh[2 * j][0], Bh[2 * j][1], Bh[2 * j + 1][0], Bh[2 * j + 1][1]);
        }
    }

#pragma unroll 1
    for (int nb = 0; nb < NTILES; nb++) {
        // 2 independent accumulation chains (even/odd kt)
        float c00 = 0.f, c01 = 0.f, c02 = 0.f, c03 = 0.f;
        float c10 = 0.f, c11 = 0.f, c12 = 0.f, c13 = 0.f;
#pragma unroll
        for (int kt = 0; kt < 16; kt += 2) {
            mma_f16(c00, c01, c02, c03, A[kt],     Bh[kt][0],     Bh[kt][1]);
            mma_f16(c10, c11, c12, c13, A[kt + 1], Bh[kt + 1][0], Bh[kt + 1][1]);
        }

        // prefetch next tile's B (WAR-safe: all reads issued) before epilogue
        if (nb + 1 < NTILES) {
            const int row = (nb + 1) * 8 + lr;
#pragma unroll
            for (int j = 0; j < 8; j++) {
                int kb = j * 64 + g * 16;
                uint32_t off = (uint32_t)((kb >> 7) * scs)
                             + sw128((uint32_t)(row * 128 + (kb & 127)));
                ldsm4(sb + srcHi + off,
                      Bh[2 * j][0], Bh[2 * j][1], Bh[2 * j + 1][0], Bh[2 * j + 1][1]);
            }
        }

        // epilogue (overlaps prefetch latency)
        float d0 = bias0 + (c00 + c10);
        float d1 = bias0 + (c01 + c11);
        float d2 = bias1 + (c02 + c12);
        float d3 = bias1 + (c03 + c13);

        const int e0 = wq * 16 + (lane >> 2);
        const int nL = nb * 8 + 2 * (lane & 3);
        if constexpr (!LAST) {
            if (nL < 2 * SPT) {
                float t0v = tanh_fast(d0), t1v = tanh_fast(d1);
                float t2v = tanh_fast(d2), t3v = tanh_fast(d3);
                int t0 = nL / SPT, ln0 = nL % SPT;
                int r0 = t0 * (SPT / 2) + (ln0 >> 1), k0 = (ln0 & 1) * 128;
                store_out(sm, dstHi, dcs, r0, k0 + e0,     t0v);
                store_out(sm, dstHi, dcs, r0, k0 + e0 + 8, t2v);
                int n1 = nL + 1, t1 = n1 / SPT, ln1 = n1 % SPT;
                int r1 = t1 * (SPT / 2) + (ln1 >> 1), k1 = (ln1 & 1) * 128;
                store_out(sm, dstHi, dcs, r1, k1 + e0,     t1v);
                store_out(sm, dstHi, dcs, r1, k1 + e0 + 8, t3v);
            }
        } else {
            if ((lane & 3) == 0) {
                rootp[e0]           = tanh_fast(d0);
                rootp[e0 + 8]       = tanh_fast(d2);
                rootp[128 + e0]     = tanh_fast(d1);
                rootp[128 + e0 + 8] = tanh_fast(d3);
            }
        }
    }
}

__global__ __launch_bounds__(256, 2)
void tree_kernel(const void* __restrict__ tokens_raw,
                 const float* __restrict__ emb,
                 const float* __restrict__ W_tree,
                 const float* __restrict__ b_tree,
                 const float* __restrict__ W_cls,
                 const float* __restrict__ b_cls,
                 float* __restrict__ out)
{
    extern __shared__ char sm[];
    const uint32_t sb = smem_u32(sm);
    const int tid = threadIdx.x, wq = tid >> 5, lane = tid & 31;
    const int b = blockIdx.x;                 // trees 2b, 2b+1

    // ---- leaf gather, MLP-8 batched: 1 token LDG/thread + shfl broadcast ----
    const int is32 = g_tok_is_i32;
    {
        const long long* t64 = (const long long*)tokens_raw;
        const int*       t32 = (const int*)tokens_raw;
        const int myLeaf = wq + 8 * lane;         // unique 0..255
        int myTok = is32 ? t32[b * 256 + myLeaf]
                         : (int)t64[b * 256 + myLeaf];
#pragma unroll
        for (int grp = 0; grp < 4; grp++) {
            float4 v[8];
#pragma unroll
            for (int j = 0; j < 8; j++) {
                int i = grp * 8 + j;              // leaf wq + 8*i
                int tk = __shfl_sync(0xffffffffu, myTok, i);
                v[j] = ((const float4*)emb)[(long long)tk * 32 + lane];
            }
#pragma unroll
            for (int j = 0; j < 8; j++) {
                int i = grp * 8 + j;
                int l = wq + 8 * i;
                int t = l >> 7, ll = l & 127;
                int row = t * 64 + (ll >> 1);
                int kb16 = ((ll & 1) << 7) + lane * 4;
                int chunk = kb16 >> 6, inner = kb16 & 63;
                uint32_t off = sw128((uint32_t)(row * 128 + inner * 2));
                char* dst = sm + OFF_B0 + chunk * B0_CS;
                *(uint32_t*)(dst + off)     = pack_h2(v[j].x, v[j].y);
                *(uint32_t*)(dst + off + 4) = pack_h2(v[j].z, v[j].w);
            }
        }
    }

    // ---- W fragments straight from global (m16n8k16 A-lane mapping), fp16 ----
    uint32_t A[16][4];
    {
        const int r0 = wq * 16 + (lane >> 2);
        const int c0 = (lane & 3) * 2;
#pragma unroll
        for (int kt = 0; kt < 16; kt++) {
            int k0 = kt * 16 + c0;
            float2 w00 = *(const float2*)(W_tree + r0 * 256 + k0);
            float2 w10 = *(const float2*)(W_tree + (r0 + 8) * 256 + k0);
            float2 w01 = *(const float2*)(W_tree + r0 * 256 + k0 + 8);
            float2 w11 = *(const float2*)(W_tree + (r0 + 8) * 256 + k0 + 8);
            A[kt][0] = pack_h2(w00.x, w00.y);
            A[kt][1] = pack_h2(w10.x, w10.y);
            A[kt][2] = pack_h2(w01.x, w01.y);
            A[kt][3] = pack_h2(w11.x, w11.y);
        }
    }
    const float bias0 = b_tree[wq * 16 + (lane >> 2)];
    const float bias1 = b_tree[wq * 16 + (lane >> 2) + 8];
    float* rootp = (float*)(sm + OFF_ROOT);
    __syncthreads();

    run_level<16, 64, false>(sm, sb, OFF_B0, B0_CS, OFF_B1, B1_CS, A, bias0, bias1, wq, lane, rootp);
    __syncthreads();
    run_level< 8, 32, false>(sm, sb, OFF_B1, B1_CS, OFF_B0, B0_CS, A, bias0, bias1, wq, lane, rootp);
    __syncthreads();
    run_level< 4, 16, false>(sm, sb, OFF_B0, B0_CS, OFF_B1, B1_CS, A, bias0, bias1, wq, lane, rootp);
    __syncthreads();
    run_level< 2,  8, false>(sm, sb, OFF_B1, B1_CS, OFF_B0, B0_CS, A, bias0, bias1, wq, lane, rootp);
    __syncthreads();
    run_level< 1,  4, false>(sm, sb, OFF_B0, B0_CS, OFF_B1, B1_CS, A, bias0, bias1, wq, lane, rootp);
    __syncthreads();
    run_level< 1,  2, false>(sm, sb, OFF_B1, B1_CS, OFF_B0, B0_CS, A, bias0, bias1, wq, lane, rootp);
    __syncthreads();
    run_level< 1,  1, true >(sm, sb, OFF_B0, B0_CS, OFF_B1, B1_CS, A, bias0, bias1, wq, lane, rootp);
    __syncthreads();

    // ---- classifier for both trees (6 warp-dots, fp32) ----
    if (tid < 192) {
        int w = tid >> 5;
        int t = (w >= 3) ? 1 : 0, o = w - t * 3;
        float p = 0.f;
#pragma unroll
        for (int k = 0; k < 4; k++) {
            int ee = lane + 32 * k;
            p += rootp[t * 128 + ee] * W_cls[o * 128 + ee];
        }
#pragma unroll
        for (int off = 16; off; off >>= 1)
            p += __shfl_down_sync(0xffffffffu, p, off);
        if (lane == 0) out[(2 * b + t) * NOUTC + o] = p + b_cls[o];
    }
}

extern "C" void kernel_launch(void* const* d_in, const int* in_sizes, int n_in,
                              void* d_out, int out_size)
{
    const void*  tokens = d_in[0];
    const float* emb    = (const float*)d_in[1];
    const float* W_tree = (const float*)d_in[2];
    const float* b_tree = (const float*)d_in[3];
    const float* W_cls  = (const float*)d_in[4];
    const float* b_cls  = (const float*)d_in[5];
    float* out = (float*)d_out;

    cudaFuncSetAttribute(tree_kernel,
                         cudaFuncAttributeMaxDynamicSharedMemorySize, SMEM_BYTES);

    detect_tok_kernel<<<1, 256>>>((const unsigned int*)tokens);
    tree_kernel<<<NB / 2, 256, SMEM_BYTES>>>(tokens, emb, W_tree, b_tree,
                                             W_cls, b_cls, out);
}